// round 11
// baseline (speedup 1.0000x reference)
#include <cuda_runtime.h>
#include <cstdint>

// Problem constants
#define TV        16384         // T * V
#define CTX       16            // T
#define VOCABSZ   1024          // V
#define NB        256           // batch
#define GROUP     16            // consecutive W rows per output group
#define NGROUPS   (TV / GROUP)  // 1024 groups
#define NSM       148           // persistent CTAs (1 per SM)
#define NBUF      3             // pipeline depth (3 x 64KB = 192KB smem)
#define ROW_BYTES (TV * 4)      // 64 KB per W row

// out[b, j] = relu( bias[j] + sum_t W[j, x[b,t] + t*V] )
//
// HBM-bound streaming of W (1 GB, read exactly once). Persistent-CTA,
// 3-stage cp.async.bulk pipeline: 148 CTAs (one per SM), each walks ~7
// groups of 16 consecutive rows with ONE continuous pipeline across group
// boundaries. Removes the ~7 wave-transition pipeline drain/refills that
// capped the non-persistent version at 85.4% DRAM duty.

extern __shared__ float s_buf[];   // NBUF * TV floats = 192 KB dynamic smem

__device__ __forceinline__ uint32_t smem_u32(const void* p) {
    return (uint32_t)__cvta_generic_to_shared(p);
}

__device__ __forceinline__ void bulk_load_row(uint32_t dst_smem,
                                              const float* src,
                                              uint32_t mbar) {
    asm volatile(
        "mbarrier.arrive.expect_tx.shared::cta.b64 _, [%0], %1;"
        :: "r"(mbar), "r"((uint32_t)ROW_BYTES) : "memory");
    asm volatile(
        "cp.async.bulk.shared::cluster.global.mbarrier::complete_tx::bytes "
        "[%0], [%1], %2, [%3];"
        :: "r"(dst_smem), "l"(src), "r"((uint32_t)ROW_BYTES), "r"(mbar)
        : "memory");
}

__device__ __forceinline__ void mbar_wait(uint32_t mbar, uint32_t phase) {
    asm volatile(
        "{\n\t"
        ".reg .pred P;\n\t"
        "WAIT_%=: mbarrier.try_wait.parity.acquire.cta.shared::cta.b64 P, [%0], %1, 0x989680;\n\t"
        "@P bra DONE_%=;\n\t"
        "bra WAIT_%=;\n\t"
        "DONE_%=:\n\t"
        "}"
        :: "r"(mbar), "r"(phase) : "memory");
}

// Flat work index q (0..n_rows-1) -> W row for this CTA.
__device__ __forceinline__ int q_to_row(int bid, int q) {
    int g = bid + (q >> 4) * NSM;       // group index, strided across CTAs
    return g * GROUP + (q & (GROUP - 1));
}

__global__ __launch_bounds__(256, 1)
void lr_persist_kernel(const int*   __restrict__ x,
                       const float* __restrict__ W,
                       const float* __restrict__ bias,
                       float*       __restrict__ out)
{
    __shared__ alignas(8) uint64_t mbar[NBUF];
    const int tid = threadIdx.x;            // = batch index b
    const int bid = blockIdx.x;

    // Groups owned by this CTA: g = bid, bid+NSM, ... < NGROUPS
    const int n_groups = (NGROUPS - bid + NSM - 1) / NSM;   // 6 or 7
    const int n_rows   = n_groups * GROUP;                  // >= 96 > NBUF

    uint32_t mb[NBUF], sb[NBUF];
    #pragma unroll
    for (int i = 0; i < NBUF; i++) {
        mb[i] = smem_u32(&mbar[i]);
        sb[i] = smem_u32(s_buf + i * TV);
    }

    if (tid == 0) {
        #pragma unroll
        for (int i = 0; i < NBUF; i++)
            asm volatile("mbarrier.init.shared::cta.b64 [%0], 1;"
                         :: "r"(mb[i]) : "memory");
        asm volatile("fence.proxy.async.shared::cta;" ::: "memory");
    }
    __syncthreads();

    // Prologue: launch copies of the first NBUF rows in this CTA's sequence.
    if (tid == 0) {
        #pragma unroll
        for (int i = 0; i < NBUF; i++)
            bulk_load_row(sb[i], W + (size_t)q_to_row(bid, i) * TV, mb[i]);
    }

    // Column indices for this batch (overlaps with prologue copies).
    // x is int32 on device (JAX default downcasts int64).
    int cols[CTX];
    {
        const int4* xb = (const int4*)(x + tid * CTX);
        #pragma unroll
        for (int q = 0; q < CTX / 4; q++) {
            int4 v = xb[q];
            cols[q * 4 + 0] = v.x + (q * 4 + 0) * VOCABSZ;
            cols[q * 4 + 1] = v.y + (q * 4 + 1) * VOCABSZ;
            cols[q * 4 + 2] = v.z + (q * 4 + 2) * VOCABSZ;
            cols[q * 4 + 3] = v.w + (q * 4 + 3) * VOCABSZ;
        }
    }

    float acc[GROUP];
    int buf = 0, phase = 0;    // completion phase of buffer `buf`

    #pragma unroll 1
    for (int q = 0; q < n_rows; q++) {
        mbar_wait(mb[buf], phase);

        const float* __restrict__ rowp = s_buf + buf * TV;
        float s = 0.f;
        #pragma unroll
        for (int t = 0; t < CTX; t++)
            s += rowp[cols[t]];
        const int r = q & (GROUP - 1);
        acc[r] = s;

        __syncthreads();    // everyone done reading this buffer

        // Keep the pipeline streaming across group boundaries.
        if (q + NBUF < n_rows && tid == 0)
            bulk_load_row(sb[buf], W + (size_t)q_to_row(bid, q + NBUF) * TV,
                          mb[buf]);

        if (++buf == NBUF) { buf = 0; phase ^= 1; }

        // Group complete: epilogue overlaps with in-flight copies.
        if (r == GROUP - 1) {
            const int j0 = (bid + (q >> 4) * NSM) * GROUP;
            size_t base = (size_t)tid * TV + j0;
            #pragma unroll
            for (int k = 0; k < GROUP; k += 4) {
                float4 bv = *(const float4*)(bias + j0 + k);
                float4 o;
                o.x = fmaxf(acc[k + 0] + bv.x, 0.f);
                o.y = fmaxf(acc[k + 1] + bv.y, 0.f);
                o.z = fmaxf(acc[k + 2] + bv.z, 0.f);
                o.w = fmaxf(acc[k + 3] + bv.w, 0.f);
                *(float4*)(out + base + k) = o;
            }
        }
    }
}

extern "C" void kernel_launch(void* const* d_in, const int* in_sizes, int n_in,
                              void* d_out, int out_size)
{
    // Identify inputs by element count:
    //   x: 256*16 = 4096 (int32), W: 16384*16384 (f32), b: 16384 (f32)
    const int*   x    = nullptr;
    const float* W    = nullptr;
    const float* bias = nullptr;
    for (int i = 0; i < n_in; i++) {
        if (in_sizes[i] == NB * CTX)          x    = (const int*)d_in[i];
        else if (in_sizes[i] == TV)           bias = (const float*)d_in[i];
        else                                  W    = (const float*)d_in[i];
    }
    float* out = (float*)d_out;

    cudaFuncSetAttribute(lr_persist_kernel,
                         cudaFuncAttributeMaxDynamicSharedMemorySize,
                         NBUF * TV * sizeof(float));

    dim3 grid(NSM);     // persistent: one CTA per SM
    dim3 block(256);
    lr_persist_kernel<<<grid, block, NBUF * TV * sizeof(float)>>>(x, W, bias, out);
}